// round 1
// baseline (speedup 1.0000x reference)
#include <cuda_runtime.h>
#include <math.h>

#define D_MODEL 1024
#define D_VOCAB 32000
#define NB 4
#define SEQ 1024
#define BT (NB * SEQ)        // 4096 rows
#define NLAYERS 6
#define BTV ((long)BT * D_VOCAB)

// ---------------- scratch (device globals; no allocation allowed) ------------
__device__ float g_z  [BT * D_MODEL];
__device__ float g_yln[BT * D_MODEL];
__device__ float g_q  [BT * D_MODEL];
__device__ float g_k  [BT * D_MODEL];
__device__ float g_v  [BT * D_MODEL];
__device__ float g_s  [NB * SEQ * SEQ];
__device__ float g_o  [BT * D_MODEL];
__device__ float g_h  [BT * D_MODEL];
__device__ float g_nll[BT];

// ---------------- embedding gather ------------------------------------------
__global__ void embed_kernel(const int* __restrict__ x, const float* __restrict__ enc,
                             float* __restrict__ z) {
    int row = blockIdx.x;
    int tok = x[row];
    const float* src = enc + (long)tok * D_MODEL;
    float* dst = z + (long)row * D_MODEL;
    for (int i = threadIdx.x; i < D_MODEL; i += blockDim.x) dst[i] = src[i];
}

// ---------------- (buggy) LayerNorm:  (x - mu/sqrt(var)) * g + b,  ddof=1 ----
__global__ void ln_kernel(const float* __restrict__ in, const float* __restrict__ gamma,
                          const float* __restrict__ beta, float* __restrict__ out) {
    int row = blockIdx.x;
    const float* xr = in + (long)row * D_MODEL;
    __shared__ float red[256];
    int tid = threadIdx.x;

    float s = 0.f;
    for (int i = tid; i < D_MODEL; i += 256) s += xr[i];
    red[tid] = s; __syncthreads();
    #pragma unroll
    for (int o = 128; o > 0; o >>= 1) { if (tid < o) red[tid] += red[tid + o]; __syncthreads(); }
    float mu = red[0] / (float)D_MODEL;
    __syncthreads();

    float s2 = 0.f;
    for (int i = tid; i < D_MODEL; i += 256) { float d = xr[i] - mu; s2 += d * d; }
    red[tid] = s2; __syncthreads();
    #pragma unroll
    for (int o = 128; o > 0; o >>= 1) { if (tid < o) red[tid] += red[tid + o]; __syncthreads(); }
    float var = red[0] / (float)(D_MODEL - 1);
    float shift = mu * rsqrtf(var);        // the bug: x - mu/sqrt(var)

    float* orow = out + (long)row * D_MODEL;
    for (int i = tid; i < D_MODEL; i += 256)
        orow[i] = (xr[i] - shift) * gamma[i] + beta[i];
}

// ---------------- row softmax over SEQ --------------------------------------
__global__ void softmax_kernel(float* __restrict__ s) {
    int row = blockIdx.x;
    float* r = s + (long)row * SEQ;
    __shared__ float red[256];
    int tid = threadIdx.x;

    float m = -1e30f;
    for (int i = tid; i < SEQ; i += 256) m = fmaxf(m, r[i]);
    red[tid] = m; __syncthreads();
    #pragma unroll
    for (int o = 128; o > 0; o >>= 1) { if (tid < o) red[tid] = fmaxf(red[tid], red[tid + o]); __syncthreads(); }
    float mx = red[0]; __syncthreads();

    float sum = 0.f;
    for (int i = tid; i < SEQ; i += 256) { float e = expf(r[i] - mx); r[i] = e; sum += e; }
    red[tid] = sum; __syncthreads();
    #pragma unroll
    for (int o = 128; o > 0; o >>= 1) { if (tid < o) red[tid] += red[tid + o]; __syncthreads(); }
    float inv = 1.f / red[0];
    for (int i = tid; i < SEQ; i += 256) r[i] *= inv;
}

// ---------------- SGEMM NN: C = A(MxK) * B(KxN)  [+bias][relu][+=C] ----------
// flags: 1=relu, 2=accumulate into C, 4=add bias
__global__ __launch_bounds__(256) void sgemm_nn(
    const float* __restrict__ A, const float* __restrict__ B,
    const float* __restrict__ bias, float* __restrict__ C,
    int M, int N, int K, long sA, long sB, long sC, int flags) {
    A += (long)blockIdx.z * sA;
    B += (long)blockIdx.z * sB;
    C += (long)blockIdx.z * sC;

    __shared__ float As[8][128];
    __shared__ float Bs[8][128];
    const int tid = threadIdx.x;
    const int row0 = blockIdx.y * 128, col0 = blockIdx.x * 128;
    const int tr = (tid / 16) * 8, tc = (tid % 16) * 8;
    const int arow = tid >> 1, acol = (tid & 1) * 4;
    const int brow = tid >> 5, bcol = (tid & 31) * 4;

    const float* Aptr = A + (long)(row0 + arow) * K + acol;
    const float* Bptr = B + (long)brow * N + col0 + bcol;

    float acc[8][8];
    #pragma unroll
    for (int i = 0; i < 8; i++)
        #pragma unroll
        for (int j = 0; j < 8; j++) acc[i][j] = 0.f;

    for (int k0 = 0; k0 < K; k0 += 8) {
        float4 a = *(const float4*)(Aptr + k0);
        As[acol + 0][arow] = a.x; As[acol + 1][arow] = a.y;
        As[acol + 2][arow] = a.z; As[acol + 3][arow] = a.w;
        *(float4*)&Bs[brow][bcol] = *(const float4*)(Bptr + (long)k0 * N);
        __syncthreads();
        #pragma unroll
        for (int kk = 0; kk < 8; kk++) {
            float ar[8], br[8];
            *(float4*)(ar)     = *(float4*)&As[kk][tr];
            *(float4*)(ar + 4) = *(float4*)&As[kk][tr + 4];
            *(float4*)(br)     = *(float4*)&Bs[kk][tc];
            *(float4*)(br + 4) = *(float4*)&Bs[kk][tc + 4];
            #pragma unroll
            for (int i = 0; i < 8; i++)
                #pragma unroll
                for (int j = 0; j < 8; j++)
                    acc[i][j] = fmaf(ar[i], br[j], acc[i][j]);
        }
        __syncthreads();
    }

    #pragma unroll
    for (int i = 0; i < 8; i++) {
        #pragma unroll
        for (int j = 0; j < 8; j++) {
            float v = acc[i][j];
            if (flags & 4) v += bias[col0 + tc + j];
            if (flags & 1) v = fmaxf(v, 0.f);
            float* cp = &C[(long)(row0 + tr + i) * N + col0 + tc + j];
            if (flags & 2) v += *cp;
            *cp = v;
        }
    }
}

// ---------------- SGEMM NT: C = alpha * A(MxK) * B(NxK)^T --------------------
__global__ __launch_bounds__(256) void sgemm_nt(
    const float* __restrict__ A, const float* __restrict__ B,
    float* __restrict__ C, int M, int N, int K,
    long sA, long sB, long sC, float alpha) {
    A += (long)blockIdx.z * sA;
    B += (long)blockIdx.z * sB;
    C += (long)blockIdx.z * sC;

    __shared__ float As[8][128];
    __shared__ float Bs[8][128];
    const int tid = threadIdx.x;
    const int row0 = blockIdx.y * 128, col0 = blockIdx.x * 128;
    const int tr = (tid / 16) * 8, tc = (tid % 16) * 8;
    const int arow = tid >> 1, acol = (tid & 1) * 4;

    const float* Aptr = A + (long)(row0 + arow) * K + acol;
    const float* Bptr = B + (long)(col0 + arow) * K + acol;

    float acc[8][8];
    #pragma unroll
    for (int i = 0; i < 8; i++)
        #pragma unroll
        for (int j = 0; j < 8; j++) acc[i][j] = 0.f;

    for (int k0 = 0; k0 < K; k0 += 8) {
        float4 a = *(const float4*)(Aptr + k0);
        As[acol + 0][arow] = a.x; As[acol + 1][arow] = a.y;
        As[acol + 2][arow] = a.z; As[acol + 3][arow] = a.w;
        float4 b = *(const float4*)(Bptr + k0);
        Bs[acol + 0][arow] = b.x; Bs[acol + 1][arow] = b.y;
        Bs[acol + 2][arow] = b.z; Bs[acol + 3][arow] = b.w;
        __syncthreads();
        #pragma unroll
        for (int kk = 0; kk < 8; kk++) {
            float ar[8], br[8];
            *(float4*)(ar)     = *(float4*)&As[kk][tr];
            *(float4*)(ar + 4) = *(float4*)&As[kk][tr + 4];
            *(float4*)(br)     = *(float4*)&Bs[kk][tc];
            *(float4*)(br + 4) = *(float4*)&Bs[kk][tc + 4];
            #pragma unroll
            for (int i = 0; i < 8; i++)
                #pragma unroll
                for (int j = 0; j < 8; j++)
                    acc[i][j] = fmaf(ar[i], br[j], acc[i][j]);
        }
        __syncthreads();
    }

    #pragma unroll
    for (int i = 0; i < 8; i++)
        #pragma unroll
        for (int j = 0; j < 8; j++)
            C[(long)(row0 + tr + i) * N + col0 + tc + j] = acc[i][j] * alpha;
}

// ---------------- per-row NLL over V=32000 ----------------------------------
__global__ void nll_kernel(const float* __restrict__ logits, const int* __restrict__ y,
                           float* __restrict__ nll) {
    int row = blockIdx.x;
    const float* r = logits + (long)row * D_VOCAB;
    __shared__ float red[256];
    int tid = threadIdx.x;

    float m = -1e30f;
    for (int i = tid; i < D_VOCAB; i += 256) m = fmaxf(m, r[i]);
    red[tid] = m; __syncthreads();
    #pragma unroll
    for (int o = 128; o > 0; o >>= 1) { if (tid < o) red[tid] = fmaxf(red[tid], red[tid + o]); __syncthreads(); }
    float mx = red[0]; __syncthreads();

    float s = 0.f;
    for (int i = tid; i < D_VOCAB; i += 256) s += expf(r[i] - mx);
    red[tid] = s; __syncthreads();
    #pragma unroll
    for (int o = 128; o > 0; o >>= 1) { if (tid < o) red[tid] += red[tid + o]; __syncthreads(); }

    if (tid == 0) nll[row] = (mx + logf(red[0])) - r[y[row]];
}

__global__ void loss_reduce_kernel(const float* __restrict__ nll, float* __restrict__ out,
                                   long ofs) {
    __shared__ float red[256];
    int tid = threadIdx.x;
    float s = 0.f;
    for (int i = tid; i < BT; i += 256) s += nll[i];
    red[tid] = s; __syncthreads();
    #pragma unroll
    for (int o = 128; o > 0; o >>= 1) { if (tid < o) red[tid] += red[tid + o]; __syncthreads(); }
    if (tid == 0) out[ofs] = red[0] / (float)BT;
}

// ---------------- driver -----------------------------------------------------
extern "C" void kernel_launch(void* const* d_in, const int* in_sizes, int n_in,
                              void* d_out, int out_size) {
    (void)in_sizes; (void)n_in;
    const int*   x   = (const int*)  d_in[0];
    const int*   y   = (const int*)  d_in[1];
    const float* enc = (const float*)d_in[2];
    const float* g1  = (const float*)d_in[3];
    const float* b1  = (const float*)d_in[4];
    const float* wq  = (const float*)d_in[5];
    const float* wk  = (const float*)d_in[6];
    const float* wv  = (const float*)d_in[7];
    const float* g2  = (const float*)d_in[8];
    const float* b2  = (const float*)d_in[9];
    const float* w1  = (const float*)d_in[10];
    const float* bb1 = (const float*)d_in[11];
    const float* w2  = (const float*)d_in[12];
    const float* bb2 = (const float*)d_in[13];
    float* out = (float*)d_out;

    float *z, *yln, *q, *k, *v, *s, *o, *h, *nll;
    cudaGetSymbolAddress((void**)&z,   g_z);
    cudaGetSymbolAddress((void**)&yln, g_yln);
    cudaGetSymbolAddress((void**)&q,   g_q);
    cudaGetSymbolAddress((void**)&k,   g_k);
    cudaGetSymbolAddress((void**)&v,   g_v);
    cudaGetSymbolAddress((void**)&s,   g_s);
    cudaGetSymbolAddress((void**)&o,   g_o);
    cudaGetSymbolAddress((void**)&h,   g_h);
    cudaGetSymbolAddress((void**)&nll, g_nll);

    const long SD = (long)SEQ * D_MODEL;   // per-batch stride within (BT, D) buffers
    const long SS = (long)SEQ * SEQ;       // per-batch stride within scores

    embed_kernel<<<BT, 256>>>(x, enc, z);

    dim3 grid_proj(D_MODEL / 128, BT / 128);      // (8, 32)
    dim3 grid_attn(SEQ / 128, SEQ / 128, NB);     // (8, 8, 4)

    for (int layer = 0; layer < NLAYERS; layer++) {
        ln_kernel<<<BT, 256>>>(z, g1, b1, yln);

        sgemm_nn<<<grid_proj, 256>>>(yln, wq, nullptr, q, BT, D_MODEL, D_MODEL, 0, 0, 0, 0);
        sgemm_nn<<<grid_proj, 256>>>(yln, wk, nullptr, k, BT, D_MODEL, D_MODEL, 0, 0, 0, 0);
        sgemm_nn<<<grid_proj, 256>>>(yln, wv, nullptr, v, BT, D_MODEL, D_MODEL, 0, 0, 0, 0);

        // S = (Q K^T) / sqrt(D)
        sgemm_nt<<<grid_attn, 256>>>(q, k, s, SEQ, SEQ, D_MODEL, SD, SD, SS, 0.03125f);

        softmax_kernel<<<NB * SEQ, 256>>>(s);

        // O = S V
        sgemm_nn<<<grid_attn, 256>>>(s, v, nullptr, o, SEQ, D_MODEL, SEQ, SS, SD, SD, 0);

        ln_kernel<<<BT, 256>>>(o, g2, b2, yln);

        // H = relu(Y W1 + b1)
        sgemm_nn<<<grid_proj, 256>>>(yln, w1, bb1, h, BT, D_MODEL, D_MODEL, 0, 0, 0, 4 | 1);
        // Z += H W2 + b2
        sgemm_nn<<<grid_proj, 256>>>(h, w2, bb2, z, BT, D_MODEL, D_MODEL, 0, 0, 0, 4 | 2);
    }

    // logits = Z enc^T   (M=4096, N=32000, K=1024)
    dim3 grid_logits(D_VOCAB / 128, BT / 128);    // (250, 32)
    sgemm_nt<<<grid_logits, 256>>>(z, enc, out, BT, D_VOCAB, D_MODEL, 0, 0, 0, 1.0f);

    // loss = mean(logsumexp - logit_y)
    nll_kernel<<<BT, 256>>>(out, y, nll);
    if ((long)out_size > BTV)
        loss_reduce_kernel<<<1, 256>>>(nll, out, BTV);
}